// round 12
// baseline (speedup 1.0000x reference)
#include <cuda_runtime.h>
#include <cuda_fp16.h>
#include <cstdint>

#define B_ 4
#define S_ 2048
#define E_ 1024
#define H_ 16
#define D_ 64
#define MTOT (B_*S_)   // 8192

// Scratch (device globals: allocation-free rule)
__device__ float g_Q[B_*S_*E_];
__device__ float g_K[B_*S_*E_];
__device__ float g_V[B_*S_*E_];
__device__ float g_Ctx[B_*S_*E_];

// ---------------------------------------------------------------------------
// helpers
// ---------------------------------------------------------------------------
// HMMA.TF32 reads the top 19 bits of an fp32 register. +0x1000 on the bit
// pattern = round-to-nearest (ties away) in 1 IADD. (== cvt.rna numerics.)
__device__ __forceinline__ uint32_t rtf(float x) {
    return __float_as_uint(x) + 0x1000u;
}

__device__ __forceinline__ void mma_tf32(float* c, const uint32_t* a,
                                         uint32_t b0, uint32_t b1) {
    asm volatile(
        "mma.sync.aligned.m16n8k8.row.col.f32.tf32.tf32.f32 "
        "{%0,%1,%2,%3}, {%4,%5,%6,%7}, {%8,%9}, {%0,%1,%2,%3};"
        : "+f"(c[0]), "+f"(c[1]), "+f"(c[2]), "+f"(c[3])
        : "r"(a[0]), "r"(a[1]), "r"(a[2]), "r"(a[3]), "r"(b0), "r"(b1));
}

// fp16 m16n8k16, fp32 accumulate (same 10-bit mantissa as tf32, 2x rate)
__device__ __forceinline__ void mma_f16(float* c, const uint32_t* a,
                                        uint32_t b0, uint32_t b1) {
    asm volatile(
        "mma.sync.aligned.m16n8k16.row.col.f32.f16.f16.f32 "
        "{%0,%1,%2,%3}, {%4,%5,%6,%7}, {%8,%9}, {%0,%1,%2,%3};"
        : "+f"(c[0]), "+f"(c[1]), "+f"(c[2]), "+f"(c[3])
        : "r"(a[0]), "r"(a[1]), "r"(a[2]), "r"(a[3]), "r"(b0), "r"(b1));
}

__device__ __forceinline__ uint32_t h2pack(float a, float b) {
    __half2 h = __floats2half2_rn(a, b);
    return *(uint32_t*)&h;
}

__device__ __forceinline__ void cp_async16(uint32_t saddr, const void* g) {
    asm volatile("cp.async.cg.shared.global [%0], [%1], 16;"
                 :: "r"(saddr), "l"(g));
}
__device__ __forceinline__ void cp_commit() {
    asm volatile("cp.async.commit_group;");
}
template <int N>
__device__ __forceinline__ void cp_wait() {
    asm volatile("cp.async.wait_group %0;" :: "n"(N));
}

// ---------------------------------------------------------------------------
// tf32 GEMM (NT): ROUND-6 VERBATIM. CTA 128x128, BK=16, 256 thr (8 warps,
// 2x4), warp tile 64x32. 3-stage cp.async, one sync per k-tile.
// ---------------------------------------------------------------------------
#define GP 20
#define GSTG (128 * GP)
#define GEMM_SMEM_FLOATS (6 * GSTG)   // As[3] + Bs[3] = 61440 B

__global__ __launch_bounds__(256) void gemm_tf32_nt(
    const float* __restrict__ A, const float* __restrict__ Bm,
    const float* __restrict__ bias, float* __restrict__ C,
    int M, int N, int K)
{
    extern __shared__ float smg[];
    float* As = smg;             // 3 buffers of GSTG
    float* Bs = smg + 3 * GSTG;

    const int tid = threadIdx.x;
    const int warp = tid >> 5, lane = tid & 31;
    const int g = lane >> 2, q = lane & 3;
    const int wm = warp >> 2;          // 0..1
    const int wn = warp & 3;           // 0..3
    const int bm = blockIdx.y, bn = blockIdx.x;

    const int lrow = tid >> 1;
    const int lcol = (tid & 1) * 8;
    const float* Ap = A + (size_t)(bm * 128 + lrow) * K + lcol;
    const float* Bp = Bm + (size_t)(bn * 128 + lrow) * K + lcol;

    uint32_t sA0 = (uint32_t)__cvta_generic_to_shared(&As[lrow * GP + lcol]);
    uint32_t sB0 = (uint32_t)__cvta_generic_to_shared(&Bs[lrow * GP + lcol]);
    const uint32_t stg = (uint32_t)(GSTG * sizeof(float));

    float acc[4][4][4];
#pragma unroll
    for (int i = 0; i < 4; i++)
#pragma unroll
        for (int j = 0; j < 4; j++)
#pragma unroll
            for (int t = 0; t < 4; t++) acc[i][j][t] = 0.f;

    const int nt = K / 16;
#pragma unroll
    for (int p = 0; p < 2; p++) {
        const float* ap = Ap + p * 16;
        const float* bp = Bp + p * 16;
        cp_async16(sA0 + p * stg, ap);
        cp_async16(sA0 + p * stg + 16, ap + 4);
        cp_async16(sB0 + p * stg, bp);
        cp_async16(sB0 + p * stg + 16, bp + 4);
        cp_commit();
    }

    for (int kt = 0; kt < nt; kt++) {
        const int cur = kt % 3;
        cp_wait<1>();
        __syncthreads();
        if (kt + 2 < nt) {
            const int nxt = (kt + 2) % 3;
            const float* ap = Ap + (kt + 2) * 16;
            const float* bp = Bp + (kt + 2) * 16;
            cp_async16(sA0 + nxt * stg, ap);
            cp_async16(sA0 + nxt * stg + 16, ap + 4);
            cp_async16(sB0 + nxt * stg, bp);
            cp_async16(sB0 + nxt * stg + 16, bp + 4);
            cp_commit();
        } else {
            cp_commit();
        }

        const float* as = As + cur * GSTG;
        const float* bs = Bs + cur * GSTG;
#pragma unroll
        for (int kh = 0; kh < 2; kh++) {
            const int k0 = kh * 8;
            uint32_t af[4][4];
#pragma unroll
            for (int i = 0; i < 4; i++) {
                int r = wm * 64 + i * 16 + g;
                af[i][0] = rtf(as[r * GP + k0 + q]);
                af[i][1] = rtf(as[(r + 8) * GP + k0 + q]);
                af[i][2] = rtf(as[r * GP + k0 + q + 4]);
                af[i][3] = rtf(as[(r + 8) * GP + k0 + q + 4]);
            }
#pragma unroll
            for (int j = 0; j < 4; j++) {
                int n = wn * 32 + j * 8 + g;
                uint32_t bf0 = rtf(bs[n * GP + k0 + q]);
                uint32_t bf1 = rtf(bs[n * GP + k0 + q + 4]);
#pragma unroll
                for (int i = 0; i < 4; i++)
                    mma_tf32(acc[i][j], af[i], bf0, bf1);
            }
        }
    }

#pragma unroll
    for (int i = 0; i < 4; i++) {
        int r0 = bm * 128 + wm * 64 + i * 16 + g;
#pragma unroll
        for (int j = 0; j < 4; j++) {
            int col = bn * 128 + wn * 32 + j * 8 + 2 * q;
            float bx = 0.f, by = 0.f;
            if (bias) { bx = bias[col]; by = bias[col + 1]; }
            float2 v0 = make_float2(acc[i][j][0] + bx, acc[i][j][1] + by);
            float2 v1 = make_float2(acc[i][j][2] + bx, acc[i][j][3] + by);
            *(float2*)&C[(size_t)r0 * N + col] = v0;
            *(float2*)&C[(size_t)(r0 + 8) * N + col] = v1;
        }
    }
}

// ---------------------------------------------------------------------------
// fp16 flash attention. BQ=128, BKV=64, 128 thr (4 warps), m32 warps,
// mma m16n8k16 (fp32 accum). Smem as half, row pitch 36 WORDS (72 halves):
// fragment-load bank = 4g+q (conflict-free). V staged TRANSPOSED
// (Vt[dim][key]) so PV B-frags are contiguous 32-bit pairs.
// smem = 13824 words = 55296 B.
// ---------------------------------------------------------------------------
#define WPITCH 36                       // 32-bit words per row (72 halves)
#define QS0 0                           // 128 rows
#define KS0 (128 * WPITCH)              // 64 rows
#define VT0 (KS0 + 64 * WPITCH)         // 64 rows (dim-major)
#define PS0 (VT0 + 64 * WPITCH)         // 128 rows
#define FLASH_SMEM_WORDS (PS0 + 128 * WPITCH)   // 13824

__global__ __launch_bounds__(128) void flash_f16_kernel(
    const float* __restrict__ Q, const float* __restrict__ K,
    const float* __restrict__ V, float* __restrict__ O)
{
    extern __shared__ uint32_t smw[];

    const int tid = threadIdx.x;
    const int warp = tid >> 5, lane = tid & 31;
    const int g = lane >> 2, q = lane & 3;
    const int b = blockIdx.z, h = blockIdx.y;
    const int q0 = blockIdx.x * 128;
    const int base = b * S_ * E_ + h * D_;
    const int r0 = warp * 32 + g;       // m-tile 0 row base
    const int r1 = r0 + 16;             // m-tile 1 row base

    // ---- stage Q [128 q][64 d] scaled 1/8, as half. 2048 float4 units. ----
#pragma unroll
    for (int t = 0; t < 16; t++) {
        int u = tid + t * 128;
        int rr = u >> 4, cc = (u & 15) * 4;
        float4 v = *(const float4*)&Q[base + (size_t)(q0 + rr) * E_ + cc];
        uint2 o = make_uint2(h2pack(v.x * 0.125f, v.y * 0.125f),
                             h2pack(v.z * 0.125f, v.w * 0.125f));
        *(uint2*)&smw[QS0 + rr * WPITCH + (cc >> 1)] = o;
    }

    float m0a = -1e30f, m0b = -1e30f, m1a = -1e30f, m1b = -1e30f;
    float l0a = 0.f, l0b = 0.f, l1a = 0.f, l1b = 0.f;
    float oacc0[8][4], oacc1[8][4];
#pragma unroll
    for (int j = 0; j < 8; j++)
#pragma unroll
        for (int t = 0; t < 4; t++) { oacc0[j][t] = 0.f; oacc1[j][t] = 0.f; }

    for (int t0 = 0; t0 < S_; t0 += 64) {
        __syncthreads();   // prior readers done (also covers Q staging, iter 0)
        // ---- K [64 key][64 d] row-major as half: 1024 float4 units ----
#pragma unroll
        for (int t = 0; t < 8; t++) {
            int u = tid + t * 128;
            int rr = u >> 4, cc = (u & 15) * 4;
            float4 kv = *(const float4*)&K[base + (size_t)(t0 + rr) * E_ + cc];
            uint2 o = make_uint2(h2pack(kv.x, kv.y), h2pack(kv.z, kv.w));
            *(uint2*)&smw[KS0 + rr * WPITCH + (cc >> 1)] = o;
        }
        // ---- V transposed: Vt[dim][key]. 512 units (2 keys x 4 dims). ----
        // kp in lane bits -> conflict-free smem stores; global reads scatter
        // across rows (L2-resident slice, DRAM at 3%: acceptable).
#pragma unroll
        for (int t = 0; t < 4; t++) {
            int v = tid + t * 128;
            int kp = (v & 15) | ((v >> 8) << 4);    // 0..31 (key pair)
            int dg = (v >> 4) & 15;                 // 0..15 (4-dim group)
            const float* g0 = &V[base + (size_t)(t0 + 2 * kp) * E_ + 4 * dg];
            float4 va = *(const float4*)g0;
            float4 vb = *(const float4*)(g0 + E_);
            smw[VT0 + (4 * dg + 0) * WPITCH + kp] = h2pack(va.x, vb.x);
            smw[VT0 + (4 * dg + 1) * WPITCH + kp] = h2pack(va.y, vb.y);
            smw[VT0 + (4 * dg + 2) * WPITCH + kp] = h2pack(va.z, vb.z);
            smw[VT0 + (4 * dg + 3) * WPITCH + kp] = h2pack(va.w, vb.w);
        }
        __syncthreads();

        // ---- S = Q @ K^T : m32 x n64, k=64 (4 k16 steps) ----
        float s0[8][4], s1[8][4];
#pragma unroll
        for (int j = 0; j < 8; j++)
#pragma unroll
            for (int t = 0; t < 4; t++) { s0[j][t] = 0.f; s1[j][t] = 0.f; }

#pragma unroll
        for (int ks = 0; ks < 4; ks++) {
            int kw = ks * 8;   // word offset of this k16 block
            uint32_t a0[4], a1[4];
            a0[0] = smw[QS0 + r0 * WPITCH + kw + q];
            a0[1] = smw[QS0 + (r0 + 8) * WPITCH + kw + q];
            a0[2] = smw[QS0 + r0 * WPITCH + kw + q + 4];
            a0[3] = smw[QS0 + (r0 + 8) * WPITCH + kw + q + 4];
            a1[0] = smw[QS0 + r1 * WPITCH + kw + q];
            a1[1] = smw[QS0 + (r1 + 8) * WPITCH + kw + q];
            a1[2] = smw[QS0 + r1 * WPITCH + kw + q + 4];
            a1[3] = smw[QS0 + (r1 + 8) * WPITCH + kw + q + 4];
#pragma unroll
            for (int j = 0; j < 8; j++) {
                int n = j * 8 + g;
                uint32_t b0 = smw[KS0 + n * WPITCH + kw + q];
                uint32_t b1 = smw[KS0 + n * WPITCH + kw + q + 4];
                mma_f16(s0[j], a0, b0, b1);
                mma_f16(s1[j], a1, b0, b1);
            }
        }

        // ---- online softmax, m-tile 0 ----
        {
            float mxa = -1e30f, mxb = -1e30f;
#pragma unroll
            for (int j = 0; j < 8; j++) {
                mxa = fmaxf(mxa, fmaxf(s0[j][0], s0[j][1]));
                mxb = fmaxf(mxb, fmaxf(s0[j][2], s0[j][3]));
            }
            mxa = fmaxf(mxa, __shfl_xor_sync(0xffffffffu, mxa, 1));
            mxa = fmaxf(mxa, __shfl_xor_sync(0xffffffffu, mxa, 2));
            mxb = fmaxf(mxb, __shfl_xor_sync(0xffffffffu, mxb, 1));
            mxb = fmaxf(mxb, __shfl_xor_sync(0xffffffffu, mxb, 2));
            float nma = fmaxf(m0a, mxa), nmb = fmaxf(m0b, mxb);
            float ala = __expf(m0a - nma), alb = __expf(m0b - nmb);
            m0a = nma; m0b = nmb;
            float rsa = 0.f, rsb = 0.f;
#pragma unroll
            for (int j = 0; j < 8; j++) {
                float p0 = __expf(s0[j][0] - nma);
                float p1 = __expf(s0[j][1] - nma);
                float p2 = __expf(s0[j][2] - nmb);
                float p3 = __expf(s0[j][3] - nmb);
                rsa += p0 + p1; rsb += p2 + p3;
                smw[PS0 + r0 * WPITCH + 4 * j + q] = h2pack(p0, p1);
                smw[PS0 + (r0 + 8) * WPITCH + 4 * j + q] = h2pack(p2, p3);
            }
            rsa += __shfl_xor_sync(0xffffffffu, rsa, 1);
            rsa += __shfl_xor_sync(0xffffffffu, rsa, 2);
            rsb += __shfl_xor_sync(0xffffffffu, rsb, 1);
            rsb += __shfl_xor_sync(0xffffffffu, rsb, 2);
            l0a = l0a * ala + rsa;
            l0b = l0b * alb + rsb;
#pragma unroll
            for (int j = 0; j < 8; j++) {
                oacc0[j][0] *= ala; oacc0[j][1] *= ala;
                oacc0[j][2] *= alb; oacc0[j][3] *= alb;
            }
        }
        // ---- online softmax, m-tile 1 ----
        {
            float mxa = -1e30f, mxb = -1e30f;
#pragma unroll
            for (int j = 0; j < 8; j++) {
                mxa = fmaxf(mxa, fmaxf(s1[j][0], s1[j][1]));
                mxb = fmaxf(mxb, fmaxf(s1[j][2], s1[j][3]));
            }
            mxa = fmaxf(mxa, __shfl_xor_sync(0xffffffffu, mxa, 1));
            mxa = fmaxf(mxa, __shfl_xor_sync(0xffffffffu, mxa, 2));
            mxb = fmaxf(mxb, __shfl_xor_sync(0xffffffffu, mxb, 1));
            mxb = fmaxf(mxb, __shfl_xor_sync(0xffffffffu, mxb, 2));
            float nma = fmaxf(m1a, mxa), nmb = fmaxf(m1b, mxb);
            float ala = __expf(m1a - nma), alb = __expf(m1b - nmb);
            m1a = nma; m1b = nmb;
            float rsa = 0.f, rsb = 0.f;
#pragma unroll
            for (int j = 0; j < 8; j++) {
                float p0 = __expf(s1[j][0] - nma);
                float p1 = __expf(s1[j][1] - nma);
                float p2 = __expf(s1[j][2] - nmb);
                float p3 = __expf(s1[j][3] - nmb);
                rsa += p0 + p1; rsb += p2 + p3;
                smw[PS0 + r1 * WPITCH + 4 * j + q] = h2pack(p0, p1);
                smw[PS0 + (r1 + 8) * WPITCH + 4 * j + q] = h2pack(p2, p3);
            }
            rsa += __shfl_xor_sync(0xffffffffu, rsa, 1);
            rsa += __shfl_xor_sync(0xffffffffu, rsa, 2);
            rsb += __shfl_xor_sync(0xffffffffu, rsb, 1);
            rsb += __shfl_xor_sync(0xffffffffu, rsb, 2);
            l1a = l1a * ala + rsa;
            l1b = l1b * alb + rsb;
#pragma unroll
            for (int j = 0; j < 8; j++) {
                oacc1[j][0] *= ala; oacc1[j][1] *= ala;
                oacc1[j][2] *= alb; oacc1[j][3] *= alb;
            }
        }
        __syncwarp();   // own-warp Ps writes -> own-warp frag reads

        // ---- O += P @ V : m32 x n64, k=64 (4 k16 steps) ----
#pragma unroll
        for (int ks = 0; ks < 4; ks++) {
            int kw = ks * 8;
            uint32_t a0[4], a1[4];
            a0[0] = smw[PS0 + r0 * WPITCH + kw + q];
            a0[1] = smw[PS0 + (r0 + 8) * WPITCH + kw + q];
            a0[2] = smw[PS0 + r0 * WPITCH + kw + q + 4];
            a0[3] = smw[PS0 + (r0 + 8) * WPITCH + kw + q + 4];
            a1[0] = smw[PS0 + r1 * WPITCH + kw + q];
            a1[1] = smw[PS0 + (r1 + 8) * WPITCH + kw + q];
            a1[2] = smw[PS0 + r1 * WPITCH + kw + q + 4];
            a1[3] = smw[PS0 + (r1 + 8) * WPITCH + kw + q + 4];
#pragma unroll
            for (int j = 0; j < 8; j++) {
                int n = j * 8 + g;
                uint32_t b0 = smw[VT0 + n * WPITCH + kw + q];
                uint32_t b1 = smw[VT0 + n * WPITCH + kw + q + 4];
                mma_f16(oacc0[j], a0, b0, b1);
                mma_f16(oacc1[j], a1, b0, b1);
            }
        }
    }

    // normalize + write ctx in [B,S,H,D] layout (fp32)
    float i0a = 1.f / l0a, i0b = 1.f / l0b, i1a = 1.f / l1a, i1b = 1.f / l1b;
#pragma unroll
    for (int j = 0; j < 8; j++) {
        int col = j * 8 + 2 * q;
        *(float2*)&O[base + (size_t)(q0 + r0) * E_ + col] =
            make_float2(oacc0[j][0] * i0a, oacc0[j][1] * i0a);
        *(float2*)&O[base + (size_t)(q0 + r0 + 8) * E_ + col] =
            make_float2(oacc0[j][2] * i0b, oacc0[j][3] * i0b);
        *(float2*)&O[base + (size_t)(q0 + r1) * E_ + col] =
            make_float2(oacc1[j][0] * i1a, oacc1[j][1] * i1a);
        *(float2*)&O[base + (size_t)(q0 + r1 + 8) * E_ + col] =
            make_float2(oacc1[j][2] * i1b, oacc1[j][3] * i1b);
    }
}

// ---------------------------------------------------------------------------
extern "C" void kernel_launch(void* const* d_in, const int* in_sizes, int n_in,
                              void* d_out, int out_size)
{
    const float* X  = (const float*)d_in[0];
    const float* Wq = (const float*)d_in[1];
    const float* Wk = (const float*)d_in[2];
    const float* Wv = (const float*)d_in[3];
    const float* Wo = (const float*)d_in[4];
    const float* bo = (const float*)d_in[5];
    float* out = (float*)d_out;

    float *Qp, *Kp, *Vp, *Cp;
    cudaGetSymbolAddress((void**)&Qp, g_Q);
    cudaGetSymbolAddress((void**)&Kp, g_K);
    cudaGetSymbolAddress((void**)&Vp, g_V);
    cudaGetSymbolAddress((void**)&Cp, g_Ctx);

    int gemm_smem = GEMM_SMEM_FLOATS * (int)sizeof(float);   // 61440
    cudaFuncSetAttribute(gemm_tf32_nt,
                         cudaFuncAttributeMaxDynamicSharedMemorySize, gemm_smem);
    int flash_smem = FLASH_SMEM_WORDS * (int)sizeof(uint32_t); // 55296
    cudaFuncSetAttribute(flash_f16_kernel,
                         cudaFuncAttributeMaxDynamicSharedMemorySize, flash_smem);

    dim3 gemm_grid(E_ / 128, MTOT / 128);   // (8, 64)
    gemm_tf32_nt<<<gemm_grid, 256, gemm_smem>>>(X, Wq, nullptr, Qp, MTOT, E_, E_);
    gemm_tf32_nt<<<gemm_grid, 256, gemm_smem>>>(X, Wk, nullptr, Kp, MTOT, E_, E_);
    gemm_tf32_nt<<<gemm_grid, 256, gemm_smem>>>(X, Wv, nullptr, Vp, MTOT, E_, E_);

    flash_f16_kernel<<<dim3(S_ / 128, H_, B_), 128, flash_smem>>>(Qp, Kp, Vp, Cp);

    gemm_tf32_nt<<<gemm_grid, 256, gemm_smem>>>(Cp, Wo, bo, out, MTOT, E_, E_);
}

// round 13
// speedup vs baseline: 1.3129x; 1.3129x over previous
#include <cuda_runtime.h>
#include <cstdint>

#define B_ 4
#define S_ 2048
#define E_ 1024
#define H_ 16
#define D_ 64
#define MTOT (B_*S_)   // 8192

// Scratch (device globals: allocation-free rule)
__device__ float g_Q[B_*S_*E_];
__device__ float g_K[B_*S_*E_];
__device__ float g_V[B_*S_*E_];
__device__ float g_Ctx[B_*S_*E_];

// ---------------------------------------------------------------------------
// helpers
// ---------------------------------------------------------------------------
// HMMA.TF32 reads the top 19 bits of an fp32 register. +0x1000 on the bit
// pattern = round-to-nearest (ties away) in 1 IADD. (== cvt.rna numerics.)
__device__ __forceinline__ uint32_t rtf(float x) {
    return __float_as_uint(x) + 0x1000u;
}

__device__ __forceinline__ void mma_tf32(float* c, const uint32_t* a,
                                         uint32_t b0, uint32_t b1) {
    asm volatile(
        "mma.sync.aligned.m16n8k8.row.col.f32.tf32.tf32.f32 "
        "{%0,%1,%2,%3}, {%4,%5,%6,%7}, {%8,%9}, {%0,%1,%2,%3};"
        : "+f"(c[0]), "+f"(c[1]), "+f"(c[2]), "+f"(c[3])
        : "r"(a[0]), "r"(a[1]), "r"(a[2]), "r"(a[3]), "r"(b0), "r"(b1));
}

__device__ __forceinline__ void cp_async16(uint32_t saddr, const void* g) {
    asm volatile("cp.async.cg.shared.global [%0], [%1], 16;"
                 :: "r"(saddr), "l"(g));
}
__device__ __forceinline__ void cp_commit() {
    asm volatile("cp.async.commit_group;");
}
template <int N>
__device__ __forceinline__ void cp_wait() {
    asm volatile("cp.async.wait_group %0;" :: "n"(N));
}

// ---------------------------------------------------------------------------
// tf32 GEMM (NT): ROUND-6 VERBATIM. CTA 128x128, BK=16, 256 thr (8 warps,
// 2x4), warp tile 64x32. 3-stage cp.async, one sync per k-tile.
// ---------------------------------------------------------------------------
#define GP 20
#define GSTG (128 * GP)
#define GEMM_SMEM_FLOATS (6 * GSTG)   // As[3] + Bs[3] = 61440 B

__global__ __launch_bounds__(256) void gemm_tf32_nt(
    const float* __restrict__ A, const float* __restrict__ Bm,
    const float* __restrict__ bias, float* __restrict__ C,
    int M, int N, int K)
{
    extern __shared__ float smg[];
    float* As = smg;             // 3 buffers of GSTG
    float* Bs = smg + 3 * GSTG;

    const int tid = threadIdx.x;
    const int warp = tid >> 5, lane = tid & 31;
    const int g = lane >> 2, q = lane & 3;
    const int wm = warp >> 2;          // 0..1
    const int wn = warp & 3;           // 0..3
    const int bm = blockIdx.y, bn = blockIdx.x;

    const int lrow = tid >> 1;
    const int lcol = (tid & 1) * 8;
    const float* Ap = A + (size_t)(bm * 128 + lrow) * K + lcol;
    const float* Bp = Bm + (size_t)(bn * 128 + lrow) * K + lcol;

    uint32_t sA0 = (uint32_t)__cvta_generic_to_shared(&As[lrow * GP + lcol]);
    uint32_t sB0 = (uint32_t)__cvta_generic_to_shared(&Bs[lrow * GP + lcol]);
    const uint32_t stg = (uint32_t)(GSTG * sizeof(float));

    float acc[4][4][4];
#pragma unroll
    for (int i = 0; i < 4; i++)
#pragma unroll
        for (int j = 0; j < 4; j++)
#pragma unroll
            for (int t = 0; t < 4; t++) acc[i][j][t] = 0.f;

    const int nt = K / 16;
#pragma unroll
    for (int p = 0; p < 2; p++) {
        const float* ap = Ap + p * 16;
        const float* bp = Bp + p * 16;
        cp_async16(sA0 + p * stg, ap);
        cp_async16(sA0 + p * stg + 16, ap + 4);
        cp_async16(sB0 + p * stg, bp);
        cp_async16(sB0 + p * stg + 16, bp + 4);
        cp_commit();
    }

    for (int kt = 0; kt < nt; kt++) {
        const int cur = kt % 3;
        cp_wait<1>();
        __syncthreads();
        if (kt + 2 < nt) {
            const int nxt = (kt + 2) % 3;
            const float* ap = Ap + (kt + 2) * 16;
            const float* bp = Bp + (kt + 2) * 16;
            cp_async16(sA0 + nxt * stg, ap);
            cp_async16(sA0 + nxt * stg + 16, ap + 4);
            cp_async16(sB0 + nxt * stg, bp);
            cp_async16(sB0 + nxt * stg + 16, bp + 4);
            cp_commit();
        } else {
            cp_commit();
        }

        const float* as = As + cur * GSTG;
        const float* bs = Bs + cur * GSTG;
#pragma unroll
        for (int kh = 0; kh < 2; kh++) {
            const int k0 = kh * 8;
            uint32_t af[4][4];
#pragma unroll
            for (int i = 0; i < 4; i++) {
                int r = wm * 64 + i * 16 + g;
                af[i][0] = rtf(as[r * GP + k0 + q]);
                af[i][1] = rtf(as[(r + 8) * GP + k0 + q]);
                af[i][2] = rtf(as[r * GP + k0 + q + 4]);
                af[i][3] = rtf(as[(r + 8) * GP + k0 + q + 4]);
            }
#pragma unroll
            for (int j = 0; j < 4; j++) {
                int n = wn * 32 + j * 8 + g;
                uint32_t bf0 = rtf(bs[n * GP + k0 + q]);
                uint32_t bf1 = rtf(bs[n * GP + k0 + q + 4]);
#pragma unroll
                for (int i = 0; i < 4; i++)
                    mma_tf32(acc[i][j], af[i], bf0, bf1);
            }
        }
    }

#pragma unroll
    for (int i = 0; i < 4; i++) {
        int r0 = bm * 128 + wm * 64 + i * 16 + g;
#pragma unroll
        for (int j = 0; j < 4; j++) {
            int col = bn * 128 + wn * 32 + j * 8 + 2 * q;
            float bx = 0.f, by = 0.f;
            if (bias) { bx = bias[col]; by = bias[col + 1]; }
            float2 v0 = make_float2(acc[i][j][0] + bx, acc[i][j][1] + by);
            float2 v1 = make_float2(acc[i][j][2] + bx, acc[i][j][3] + by);
            *(float2*)&C[(size_t)r0 * N + col] = v0;
            *(float2*)&C[(size_t)(r0 + 8) * N + col] = v1;
        }
    }
}

// ---------------------------------------------------------------------------
// tf32 flash attention — round-6 body, made PERSISTENT.
// Grid = 304 CTAs (2/SM); each loops over the 1024 (b,h,q0) tiles with
// stride gridDim.x. Moves tail quantization from slot level (3.46->4,
// ~13% loss) to SM level (6.74->7, ~4%).
// One extra __syncthreads at tile top: a fast warp must not restage Qs
// while a slow warp still reads it in the last QK^T of the prior tile.
// BQ=128, BKV=64, 128 threads, m32 warps. smem 105472 B -> 2 CTAs/SM.
// ---------------------------------------------------------------------------
#define QP 68
#define VP 72
#define FLASH_SMEM_FLOATS (128*QP + 64*QP + 64*VP + 128*QP)   // 26368
#define FLASH_TILES ((S_/128) * H_ * B_)                      // 1024
#define FLASH_GRID 304

__global__ __launch_bounds__(128) void flash_tf32_kernel(
    const float* __restrict__ Q, const float* __restrict__ K,
    const float* __restrict__ V, float* __restrict__ O)
{
    extern __shared__ float sm[];
    float* Qs = sm;                    // [128][QP]
    float* Ks = Qs + 128 * QP;         // [64][QP]
    float* Vs = Ks + 64 * QP;          // [64][VP]
    float* Ps = Vs + 64 * VP;          // [128][QP]

    const int tid = threadIdx.x;
    const int warp = tid >> 5, lane = tid & 31;
    const int g = lane >> 2, q = lane & 3;
    const int r0 = warp * 32 + g;
    const int r1 = r0 + 16;

    for (int tile = blockIdx.x; tile < FLASH_TILES; tile += gridDim.x) {
        const int qb = tile & 15;              // S_/128 = 16 q-tiles
        const int h = (tile >> 4) & 15;        // H_ = 16
        const int b = tile >> 8;               // B_ = 4
        const int q0 = qb * 128;
        const int base = b * S_ * E_ + h * D_;

        __syncthreads();   // prior tile's Qs readers done before restage

#pragma unroll
        for (int t = 0; t < 16; t++) {
            int u = tid + t * 128;
            int rr = u >> 4, cc = (u & 15) * 4;
            float4 v = *(const float4*)&Q[base + (size_t)(q0 + rr) * E_ + cc];
            uint4 o;
            o.x = rtf(v.x * 0.125f); o.y = rtf(v.y * 0.125f);
            o.z = rtf(v.z * 0.125f); o.w = rtf(v.w * 0.125f);
            *(uint4*)&Qs[rr * QP + cc] = o;
        }

        float m0a = -1e30f, m0b = -1e30f, m1a = -1e30f, m1b = -1e30f;
        float l0a = 0.f, l0b = 0.f, l1a = 0.f, l1b = 0.f;
        float oacc0[8][4], oacc1[8][4];
#pragma unroll
        for (int j = 0; j < 8; j++)
#pragma unroll
            for (int t = 0; t < 4; t++) { oacc0[j][t] = 0.f; oacc1[j][t] = 0.f; }

        for (int t0 = 0; t0 < S_; t0 += 64) {
            __syncthreads();   // prior-iter Ks/Vs readers done; covers Q stage
#pragma unroll
            for (int t = 0; t < 8; t++) {
                int u = tid + t * 128;
                int rr = u >> 4, cc = (u & 15) * 4;
                float4 kv = *(const float4*)&K[base + (size_t)(t0 + rr) * E_ + cc];
                float4 vv = *(const float4*)&V[base + (size_t)(t0 + rr) * E_ + cc];
                uint4 ko, vo;
                ko.x = rtf(kv.x); ko.y = rtf(kv.y); ko.z = rtf(kv.z); ko.w = rtf(kv.w);
                vo.x = rtf(vv.x); vo.y = rtf(vv.y); vo.z = rtf(vv.z); vo.w = rtf(vv.w);
                *(uint4*)&Ks[rr * QP + cc] = ko;
                *(uint4*)&Vs[rr * VP + cc] = vo;
            }
            __syncthreads();

            float s0[8][4], s1[8][4];
#pragma unroll
            for (int j = 0; j < 8; j++)
#pragma unroll
                for (int t = 0; t < 4; t++) { s0[j][t] = 0.f; s1[j][t] = 0.f; }

#pragma unroll
            for (int ks = 0; ks < 8; ks++) {
                int k0 = ks * 8;
                uint32_t a0[4], a1[4];
                a0[0] = __float_as_uint(Qs[r0 * QP + k0 + q]);
                a0[1] = __float_as_uint(Qs[(r0 + 8) * QP + k0 + q]);
                a0[2] = __float_as_uint(Qs[r0 * QP + k0 + q + 4]);
                a0[3] = __float_as_uint(Qs[(r0 + 8) * QP + k0 + q + 4]);
                a1[0] = __float_as_uint(Qs[r1 * QP + k0 + q]);
                a1[1] = __float_as_uint(Qs[(r1 + 8) * QP + k0 + q]);
                a1[2] = __float_as_uint(Qs[r1 * QP + k0 + q + 4]);
                a1[3] = __float_as_uint(Qs[(r1 + 8) * QP + k0 + q + 4]);
#pragma unroll
                for (int j = 0; j < 8; j++) {
                    int n = j * 8 + g;
                    uint32_t b0 = __float_as_uint(Ks[n * QP + k0 + q]);
                    uint32_t b1 = __float_as_uint(Ks[n * QP + k0 + q + 4]);
                    mma_tf32(s0[j], a0, b0, b1);
                    mma_tf32(s1[j], a1, b0, b1);
                }
            }

            {
                float mxa = -1e30f, mxb = -1e30f;
#pragma unroll
                for (int j = 0; j < 8; j++) {
                    mxa = fmaxf(mxa, fmaxf(s0[j][0], s0[j][1]));
                    mxb = fmaxf(mxb, fmaxf(s0[j][2], s0[j][3]));
                }
                mxa = fmaxf(mxa, __shfl_xor_sync(0xffffffffu, mxa, 1));
                mxa = fmaxf(mxa, __shfl_xor_sync(0xffffffffu, mxa, 2));
                mxb = fmaxf(mxb, __shfl_xor_sync(0xffffffffu, mxb, 1));
                mxb = fmaxf(mxb, __shfl_xor_sync(0xffffffffu, mxb, 2));
                float nma = fmaxf(m0a, mxa), nmb = fmaxf(m0b, mxb);
                float ala = __expf(m0a - nma), alb = __expf(m0b - nmb);
                m0a = nma; m0b = nmb;
                float rsa = 0.f, rsb = 0.f;
#pragma unroll
                for (int j = 0; j < 8; j++) {
                    float p0 = __expf(s0[j][0] - nma);
                    float p1 = __expf(s0[j][1] - nma);
                    float p2 = __expf(s0[j][2] - nmb);
                    float p3 = __expf(s0[j][3] - nmb);
                    rsa += p0 + p1; rsb += p2 + p3;
                    *(uint2*)&Ps[r0 * QP + j * 8 + 2 * q] = make_uint2(rtf(p0), rtf(p1));
                    *(uint2*)&Ps[(r0 + 8) * QP + j * 8 + 2 * q] = make_uint2(rtf(p2), rtf(p3));
                }
                rsa += __shfl_xor_sync(0xffffffffu, rsa, 1);
                rsa += __shfl_xor_sync(0xffffffffu, rsa, 2);
                rsb += __shfl_xor_sync(0xffffffffu, rsb, 1);
                rsb += __shfl_xor_sync(0xffffffffu, rsb, 2);
                l0a = l0a * ala + rsa;
                l0b = l0b * alb + rsb;
#pragma unroll
                for (int j = 0; j < 8; j++) {
                    oacc0[j][0] *= ala; oacc0[j][1] *= ala;
                    oacc0[j][2] *= alb; oacc0[j][3] *= alb;
                }
            }
            {
                float mxa = -1e30f, mxb = -1e30f;
#pragma unroll
                for (int j = 0; j < 8; j++) {
                    mxa = fmaxf(mxa, fmaxf(s1[j][0], s1[j][1]));
                    mxb = fmaxf(mxb, fmaxf(s1[j][2], s1[j][3]));
                }
                mxa = fmaxf(mxa, __shfl_xor_sync(0xffffffffu, mxa, 1));
                mxa = fmaxf(mxa, __shfl_xor_sync(0xffffffffu, mxa, 2));
                mxb = fmaxf(mxb, __shfl_xor_sync(0xffffffffu, mxb, 1));
                mxb = fmaxf(mxb, __shfl_xor_sync(0xffffffffu, mxb, 2));
                float nma = fmaxf(m1a, mxa), nmb = fmaxf(m1b, mxb);
                float ala = __expf(m1a - nma), alb = __expf(m1b - nmb);
                m1a = nma; m1b = nmb;
                float rsa = 0.f, rsb = 0.f;
#pragma unroll
                for (int j = 0; j < 8; j++) {
                    float p0 = __expf(s1[j][0] - nma);
                    float p1 = __expf(s1[j][1] - nma);
                    float p2 = __expf(s1[j][2] - nmb);
                    float p3 = __expf(s1[j][3] - nmb);
                    rsa += p0 + p1; rsb += p2 + p3;
                    *(uint2*)&Ps[r1 * QP + j * 8 + 2 * q] = make_uint2(rtf(p0), rtf(p1));
                    *(uint2*)&Ps[(r1 + 8) * QP + j * 8 + 2 * q] = make_uint2(rtf(p2), rtf(p3));
                }
                rsa += __shfl_xor_sync(0xffffffffu, rsa, 1);
                rsa += __shfl_xor_sync(0xffffffffu, rsa, 2);
                rsb += __shfl_xor_sync(0xffffffffu, rsb, 1);
                rsb += __shfl_xor_sync(0xffffffffu, rsb, 2);
                l1a = l1a * ala + rsa;
                l1b = l1b * alb + rsb;
#pragma unroll
                for (int j = 0; j < 8; j++) {
                    oacc1[j][0] *= ala; oacc1[j][1] *= ala;
                    oacc1[j][2] *= alb; oacc1[j][3] *= alb;
                }
            }
            __syncwarp();

#pragma unroll
            for (int ks = 0; ks < 8; ks++) {
                int k0 = ks * 8;
                uint32_t a0[4], a1[4];
                a0[0] = __float_as_uint(Ps[r0 * QP + k0 + q]);
                a0[1] = __float_as_uint(Ps[(r0 + 8) * QP + k0 + q]);
                a0[2] = __float_as_uint(Ps[r0 * QP + k0 + q + 4]);
                a0[3] = __float_as_uint(Ps[(r0 + 8) * QP + k0 + q + 4]);
                a1[0] = __float_as_uint(Ps[r1 * QP + k0 + q]);
                a1[1] = __float_as_uint(Ps[(r1 + 8) * QP + k0 + q]);
                a1[2] = __float_as_uint(Ps[r1 * QP + k0 + q + 4]);
                a1[3] = __float_as_uint(Ps[(r1 + 8) * QP + k0 + q + 4]);
#pragma unroll
                for (int j = 0; j < 8; j++) {
                    uint32_t b0 = __float_as_uint(Vs[(k0 + q) * VP + j * 8 + g]);
                    uint32_t b1 = __float_as_uint(Vs[(k0 + q + 4) * VP + j * 8 + g]);
                    mma_tf32(oacc0[j], a0, b0, b1);
                    mma_tf32(oacc1[j], a1, b0, b1);
                }
            }
        }

        float i0a = 1.f / l0a, i0b = 1.f / l0b, i1a = 1.f / l1a, i1b = 1.f / l1b;
#pragma unroll
        for (int j = 0; j < 8; j++) {
            int col = j * 8 + 2 * q;
            *(float2*)&O[base + (size_t)(q0 + r0) * E_ + col] =
                make_float2(oacc0[j][0] * i0a, oacc0[j][1] * i0a);
            *(float2*)&O[base + (size_t)(q0 + r0 + 8) * E_ + col] =
                make_float2(oacc0[j][2] * i0b, oacc0[j][3] * i0b);
            *(float2*)&O[base + (size_t)(q0 + r1) * E_ + col] =
                make_float2(oacc1[j][0] * i1a, oacc1[j][1] * i1a);
            *(float2*)&O[base + (size_t)(q0 + r1 + 8) * E_ + col] =
                make_float2(oacc1[j][2] * i1b, oacc1[j][3] * i1b);
        }
    }
}

// ---------------------------------------------------------------------------
extern "C" void kernel_launch(void* const* d_in, const int* in_sizes, int n_in,
                              void* d_out, int out_size)
{
    const float* X  = (const float*)d_in[0];
    const float* Wq = (const float*)d_in[1];
    const float* Wk = (const float*)d_in[2];
    const float* Wv = (const float*)d_in[3];
    const float* Wo = (const float*)d_in[4];
    const float* bo = (const float*)d_in[5];
    float* out = (float*)d_out;

    float *Qp, *Kp, *Vp, *Cp;
    cudaGetSymbolAddress((void**)&Qp, g_Q);
    cudaGetSymbolAddress((void**)&Kp, g_K);
    cudaGetSymbolAddress((void**)&Vp, g_V);
    cudaGetSymbolAddress((void**)&Cp, g_Ctx);

    int gemm_smem = GEMM_SMEM_FLOATS * (int)sizeof(float);   // 61440
    cudaFuncSetAttribute(gemm_tf32_nt,
                         cudaFuncAttributeMaxDynamicSharedMemorySize, gemm_smem);
    int flash_smem = FLASH_SMEM_FLOATS * (int)sizeof(float); // 105472
    cudaFuncSetAttribute(flash_tf32_kernel,
                         cudaFuncAttributeMaxDynamicSharedMemorySize, flash_smem);

    dim3 gemm_grid(E_ / 128, MTOT / 128);   // (8, 64)
    gemm_tf32_nt<<<gemm_grid, 256, gemm_smem>>>(X, Wq, nullptr, Qp, MTOT, E_, E_);
    gemm_tf32_nt<<<gemm_grid, 256, gemm_smem>>>(X, Wk, nullptr, Kp, MTOT, E_, E_);
    gemm_tf32_nt<<<gemm_grid, 256, gemm_smem>>>(X, Wv, nullptr, Vp, MTOT, E_, E_);

    flash_tf32_kernel<<<FLASH_GRID, 128, flash_smem>>>(Qp, Kp, Vp, Cp);

    gemm_tf32_nt<<<gemm_grid, 256, gemm_smem>>>(Cp, Wo, bo, out, MTOT, E_, E_);
}

// round 14
// speedup vs baseline: 1.5446x; 1.1765x over previous
#include <cuda_runtime.h>
#include <cstdint>

#define B_ 4
#define S_ 2048
#define E_ 1024
#define H_ 16
#define D_ 64
#define MTOT (B_*S_)   // 8192

// Scratch (device globals: allocation-free rule)
__device__ float g_Q[B_*S_*E_];
__device__ float g_K[B_*S_*E_];
__device__ float g_V[B_*S_*E_];
__device__ float g_Ctx[B_*S_*E_];

// ---------------------------------------------------------------------------
// helpers
// ---------------------------------------------------------------------------
// HMMA.TF32 reads the top 19 bits of an fp32 register. +0x1000 on the bit
// pattern = round-to-nearest (ties away) in 1 IADD. (== cvt.rna numerics.)
__device__ __forceinline__ uint32_t rtf(float x) {
    return __float_as_uint(x) + 0x1000u;
}

__device__ __forceinline__ void mma_tf32(float* c, const uint32_t* a,
                                         uint32_t b0, uint32_t b1) {
    asm volatile(
        "mma.sync.aligned.m16n8k8.row.col.f32.tf32.tf32.f32 "
        "{%0,%1,%2,%3}, {%4,%5,%6,%7}, {%8,%9}, {%0,%1,%2,%3};"
        : "+f"(c[0]), "+f"(c[1]), "+f"(c[2]), "+f"(c[3])
        : "r"(a[0]), "r"(a[1]), "r"(a[2]), "r"(a[3]), "r"(b0), "r"(b1));
}

__device__ __forceinline__ void cp_async16(uint32_t saddr, const void* g) {
    asm volatile("cp.async.cg.shared.global [%0], [%1], 16;"
                 :: "r"(saddr), "l"(g));
}
__device__ __forceinline__ void cp_commit() {
    asm volatile("cp.async.commit_group;");
}
template <int N>
__device__ __forceinline__ void cp_wait() {
    asm volatile("cp.async.wait_group %0;" :: "n"(N));
}

// ---------------------------------------------------------------------------
// tf32 GEMM (NT): ROUND-6 VERBATIM (147us/GEMM proven). CTA 128x128, BK=16,
// 256 thr (8 warps, 2x4), warp tile 64x32. 3-stage cp.async, one sync/k-tile.
// ---------------------------------------------------------------------------
#define GP 20
#define GSTG (128 * GP)
#define GEMM_SMEM_FLOATS (6 * GSTG)   // As[3] + Bs[3] = 61440 B

__global__ __launch_bounds__(256) void gemm_tf32_nt(
    const float* __restrict__ A, const float* __restrict__ Bm,
    const float* __restrict__ bias, float* __restrict__ C,
    int M, int N, int K)
{
    extern __shared__ float smg[];
    float* As = smg;             // 3 buffers of GSTG
    float* Bs = smg + 3 * GSTG;

    const int tid = threadIdx.x;
    const int warp = tid >> 5, lane = tid & 31;
    const int g = lane >> 2, q = lane & 3;
    const int wm = warp >> 2;          // 0..1
    const int wn = warp & 3;           // 0..3
    const int bm = blockIdx.y, bn = blockIdx.x;

    const int lrow = tid >> 1;
    const int lcol = (tid & 1) * 8;
    const float* Ap = A + (size_t)(bm * 128 + lrow) * K + lcol;
    const float* Bp = Bm + (size_t)(bn * 128 + lrow) * K + lcol;

    uint32_t sA0 = (uint32_t)__cvta_generic_to_shared(&As[lrow * GP + lcol]);
    uint32_t sB0 = (uint32_t)__cvta_generic_to_shared(&Bs[lrow * GP + lcol]);
    const uint32_t stg = (uint32_t)(GSTG * sizeof(float));

    float acc[4][4][4];
#pragma unroll
    for (int i = 0; i < 4; i++)
#pragma unroll
        for (int j = 0; j < 4; j++)
#pragma unroll
            for (int t = 0; t < 4; t++) acc[i][j][t] = 0.f;

    const int nt = K / 16;
#pragma unroll
    for (int p = 0; p < 2; p++) {
        const float* ap = Ap + p * 16;
        const float* bp = Bp + p * 16;
        cp_async16(sA0 + p * stg, ap);
        cp_async16(sA0 + p * stg + 16, ap + 4);
        cp_async16(sB0 + p * stg, bp);
        cp_async16(sB0 + p * stg + 16, bp + 4);
        cp_commit();
    }

    for (int kt = 0; kt < nt; kt++) {
        const int cur = kt % 3;
        cp_wait<1>();
        __syncthreads();
        if (kt + 2 < nt) {
            const int nxt = (kt + 2) % 3;
            const float* ap = Ap + (kt + 2) * 16;
            const float* bp = Bp + (kt + 2) * 16;
            cp_async16(sA0 + nxt * stg, ap);
            cp_async16(sA0 + nxt * stg + 16, ap + 4);
            cp_async16(sB0 + nxt * stg, bp);
            cp_async16(sB0 + nxt * stg + 16, bp + 4);
            cp_commit();
        } else {
            cp_commit();
        }

        const float* as = As + cur * GSTG;
        const float* bs = Bs + cur * GSTG;
#pragma unroll
        for (int kh = 0; kh < 2; kh++) {
            const int k0 = kh * 8;
            uint32_t af[4][4];
#pragma unroll
            for (int i = 0; i < 4; i++) {
                int r = wm * 64 + i * 16 + g;
                af[i][0] = rtf(as[r * GP + k0 + q]);
                af[i][1] = rtf(as[(r + 8) * GP + k0 + q]);
                af[i][2] = rtf(as[r * GP + k0 + q + 4]);
                af[i][3] = rtf(as[(r + 8) * GP + k0 + q + 4]);
            }
#pragma unroll
            for (int j = 0; j < 4; j++) {
                int n = wn * 32 + j * 8 + g;
                uint32_t bf0 = rtf(bs[n * GP + k0 + q]);
                uint32_t bf1 = rtf(bs[n * GP + k0 + q + 4]);
#pragma unroll
                for (int i = 0; i < 4; i++)
                    mma_tf32(acc[i][j], af[i], bf0, bf1);
            }
        }
    }

#pragma unroll
    for (int i = 0; i < 4; i++) {
        int r0 = bm * 128 + wm * 64 + i * 16 + g;
#pragma unroll
        for (int j = 0; j < 4; j++) {
            int col = bn * 128 + wn * 32 + j * 8 + 2 * q;
            float bx = 0.f, by = 0.f;
            if (bias) { bx = bias[col]; by = bias[col + 1]; }
            float2 v0 = make_float2(acc[i][j][0] + bx, acc[i][j][1] + by);
            float2 v1 = make_float2(acc[i][j][2] + bx, acc[i][j][3] + by);
            *(float2*)&C[(size_t)r0 * N + col] = v0;
            *(float2*)&C[(size_t)(r0 + 8) * N + col] = v1;
        }
    }
}

// ---------------------------------------------------------------------------
// tf32 flash attention — round-6 structure (BQ=128, BKV=64, 128 thr, m32
// warps, grid 1024) with cp.async-pipelined K/V staging:
//   K(t+1) issued after QK^T(t) frees Ks -> load overlaps softmax+PV(t).
//   V(t+1) issued after PV(t) frees Vs  -> load overlaps QK^T(t+1).
// RN rounding moves to K/V FRAGMENT loads (bit-identical numerics).
// Q/P still rounded at staging/write. Commit/wait<1> alternation; empty
// commits at the tail keep group counts aligned.
// Pitches: Qs/Ks/Ps 68, Vs 72 (conflict-free). smem 105472 B -> 2 CTAs/SM.
// ---------------------------------------------------------------------------
#define QP 68
#define VP 72
#define FLASH_SMEM_FLOATS (128*QP + 64*QP + 64*VP + 128*QP)   // 26368

__global__ __launch_bounds__(128) void flash_tf32_kernel(
    const float* __restrict__ Q, const float* __restrict__ K,
    const float* __restrict__ V, float* __restrict__ O)
{
    extern __shared__ float sm[];
    float* Qs = sm;                    // [128][QP]
    float* Ks = Qs + 128 * QP;         // [64][QP]
    float* Vs = Ks + 64 * QP;          // [64][VP]
    float* Ps = Vs + 64 * VP;          // [128][QP]

    const int tid = threadIdx.x;
    const int warp = tid >> 5, lane = tid & 31;
    const int g = lane >> 2, q = lane & 3;
    const int b = blockIdx.z, h = blockIdx.y;
    const int q0 = blockIdx.x * 128;
    const int base = b * S_ * E_ + h * D_;
    const int r0 = warp * 32 + g;
    const int r1 = r0 + 16;

    // Stage Q tile [128 q][64 d], scaled by 1/8 (exact) + RN bias.
#pragma unroll
    for (int t = 0; t < 16; t++) {
        int u = tid + t * 128;
        int rr = u >> 4, cc = (u & 15) * 4;
        float4 v = *(const float4*)&Q[base + (size_t)(q0 + rr) * E_ + cc];
        uint4 o;
        o.x = rtf(v.x * 0.125f); o.y = rtf(v.y * 0.125f);
        o.z = rtf(v.z * 0.125f); o.w = rtf(v.w * 0.125f);
        *(uint4*)&Qs[rr * QP + cc] = o;
    }

    const uint32_t sKs = (uint32_t)__cvta_generic_to_shared(Ks);
    const uint32_t sVs = (uint32_t)__cvta_generic_to_shared(Vs);

    // prologue: async-stage K(0) then V(0) as separate groups
#pragma unroll
    for (int t = 0; t < 8; t++) {
        int u = tid + t * 128;
        int rr = u >> 4, cc = (u & 15) * 4;
        cp_async16(sKs + (uint32_t)(rr * QP + cc) * 4u,
                   &K[base + (size_t)rr * E_ + cc]);
    }
    cp_commit();
#pragma unroll
    for (int t = 0; t < 8; t++) {
        int u = tid + t * 128;
        int rr = u >> 4, cc = (u & 15) * 4;
        cp_async16(sVs + (uint32_t)(rr * VP + cc) * 4u,
                   &V[base + (size_t)rr * E_ + cc]);
    }
    cp_commit();

    float m0a = -1e30f, m0b = -1e30f, m1a = -1e30f, m1b = -1e30f;
    float l0a = 0.f, l0b = 0.f, l1a = 0.f, l1b = 0.f;
    float oacc0[8][4], oacc1[8][4];
#pragma unroll
    for (int j = 0; j < 8; j++)
#pragma unroll
        for (int t = 0; t < 4; t++) { oacc0[j][t] = 0.f; oacc1[j][t] = 0.f; }

    for (int t0 = 0; t0 < S_; t0 += 64) {
        // K(t) resident (V(t) may still be in flight); also orders Qs staging
        cp_wait<1>();
        __syncthreads();

        // ---- S = Q @ K^T (m32 x n64, k=64); RN bias on K frags ----
        float s0[8][4], s1[8][4];
#pragma unroll
        for (int j = 0; j < 8; j++)
#pragma unroll
            for (int t = 0; t < 4; t++) { s0[j][t] = 0.f; s1[j][t] = 0.f; }

#pragma unroll
        for (int ks = 0; ks < 8; ks++) {
            int k0 = ks * 8;
            uint32_t a0[4], a1[4];
            a0[0] = __float_as_uint(Qs[r0 * QP + k0 + q]);
            a0[1] = __float_as_uint(Qs[(r0 + 8) * QP + k0 + q]);
            a0[2] = __float_as_uint(Qs[r0 * QP + k0 + q + 4]);
            a0[3] = __float_as_uint(Qs[(r0 + 8) * QP + k0 + q + 4]);
            a1[0] = __float_as_uint(Qs[r1 * QP + k0 + q]);
            a1[1] = __float_as_uint(Qs[(r1 + 8) * QP + k0 + q]);
            a1[2] = __float_as_uint(Qs[r1 * QP + k0 + q + 4]);
            a1[3] = __float_as_uint(Qs[(r1 + 8) * QP + k0 + q + 4]);
#pragma unroll
            for (int j = 0; j < 8; j++) {
                int n = j * 8 + g;
                uint32_t b0 = rtf(Ks[n * QP + k0 + q]);
                uint32_t b1 = rtf(Ks[n * QP + k0 + q + 4]);
                mma_tf32(s0[j], a0, b0, b1);
                mma_tf32(s1[j], a1, b0, b1);
            }
        }

        __syncthreads();   // all warps done reading Ks
        if (t0 + 64 < S_) {     // async-stage K(t+1); overlaps softmax+PV
#pragma unroll
            for (int t = 0; t < 8; t++) {
                int u = tid + t * 128;
                int rr = u >> 4, cc = (u & 15) * 4;
                cp_async16(sKs + (uint32_t)(rr * QP + cc) * 4u,
                           &K[base + (size_t)(t0 + 64 + rr) * E_ + cc]);
            }
        }
        cp_commit();       // (empty at tail keeps group counts aligned)

        // ---- online softmax, m-tile 0 ----
        {
            float mxa = -1e30f, mxb = -1e30f;
#pragma unroll
            for (int j = 0; j < 8; j++) {
                mxa = fmaxf(mxa, fmaxf(s0[j][0], s0[j][1]));
                mxb = fmaxf(mxb, fmaxf(s0[j][2], s0[j][3]));
            }
            mxa = fmaxf(mxa, __shfl_xor_sync(0xffffffffu, mxa, 1));
            mxa = fmaxf(mxa, __shfl_xor_sync(0xffffffffu, mxa, 2));
            mxb = fmaxf(mxb, __shfl_xor_sync(0xffffffffu, mxb, 1));
            mxb = fmaxf(mxb, __shfl_xor_sync(0xffffffffu, mxb, 2));
            float nma = fmaxf(m0a, mxa), nmb = fmaxf(m0b, mxb);
            float ala = __expf(m0a - nma), alb = __expf(m0b - nmb);
            m0a = nma; m0b = nmb;
            float rsa = 0.f, rsb = 0.f;
#pragma unroll
            for (int j = 0; j < 8; j++) {
                float p0 = __expf(s0[j][0] - nma);
                float p1 = __expf(s0[j][1] - nma);
                float p2 = __expf(s0[j][2] - nmb);
                float p3 = __expf(s0[j][3] - nmb);
                rsa += p0 + p1; rsb += p2 + p3;
                *(uint2*)&Ps[r0 * QP + j * 8 + 2 * q] = make_uint2(rtf(p0), rtf(p1));
                *(uint2*)&Ps[(r0 + 8) * QP + j * 8 + 2 * q] = make_uint2(rtf(p2), rtf(p3));
            }
            rsa += __shfl_xor_sync(0xffffffffu, rsa, 1);
            rsa += __shfl_xor_sync(0xffffffffu, rsa, 2);
            rsb += __shfl_xor_sync(0xffffffffu, rsb, 1);
            rsb += __shfl_xor_sync(0xffffffffu, rsb, 2);
            l0a = l0a * ala + rsa;
            l0b = l0b * alb + rsb;
#pragma unroll
            for (int j = 0; j < 8; j++) {
                oacc0[j][0] *= ala; oacc0[j][1] *= ala;
                oacc0[j][2] *= alb; oacc0[j][3] *= alb;
            }
        }
        // ---- online softmax, m-tile 1 ----
        {
            float mxa = -1e30f, mxb = -1e30f;
#pragma unroll
            for (int j = 0; j < 8; j++) {
                mxa = fmaxf(mxa, fmaxf(s1[j][0], s1[j][1]));
                mxb = fmaxf(mxb, fmaxf(s1[j][2], s1[j][3]));
            }
            mxa = fmaxf(mxa, __shfl_xor_sync(0xffffffffu, mxa, 1));
            mxa = fmaxf(mxa, __shfl_xor_sync(0xffffffffu, mxa, 2));
            mxb = fmaxf(mxb, __shfl_xor_sync(0xffffffffu, mxb, 1));
            mxb = fmaxf(mxb, __shfl_xor_sync(0xffffffffu, mxb, 2));
            float nma = fmaxf(m1a, mxa), nmb = fmaxf(m1b, mxb);
            float ala = __expf(m1a - nma), alb = __expf(m1b - nmb);
            m1a = nma; m1b = nmb;
            float rsa = 0.f, rsb = 0.f;
#pragma unroll
            for (int j = 0; j < 8; j++) {
                float p0 = __expf(s1[j][0] - nma);
                float p1 = __expf(s1[j][1] - nma);
                float p2 = __expf(s1[j][2] - nmb);
                float p3 = __expf(s1[j][3] - nmb);
                rsa += p0 + p1; rsb += p2 + p3;
                *(uint2*)&Ps[r1 * QP + j * 8 + 2 * q] = make_uint2(rtf(p0), rtf(p1));
                *(uint2*)&Ps[(r1 + 8) * QP + j * 8 + 2 * q] = make_uint2(rtf(p2), rtf(p3));
            }
            rsa += __shfl_xor_sync(0xffffffffu, rsa, 1);
            rsa += __shfl_xor_sync(0xffffffffu, rsa, 2);
            rsb += __shfl_xor_sync(0xffffffffu, rsb, 1);
            rsb += __shfl_xor_sync(0xffffffffu, rsb, 2);
            l1a = l1a * ala + rsa;
            l1b = l1b * alb + rsb;
#pragma unroll
            for (int j = 0; j < 8; j++) {
                oacc1[j][0] *= ala; oacc1[j][1] *= ala;
                oacc1[j][2] *= alb; oacc1[j][3] *= alb;
            }
        }

        // V(t) resident (K(t+1) may still be in flight); also orders Ps writes
        cp_wait<1>();
        __syncthreads();

        // ---- O += P @ V (m32 x n64, k=64); RN bias on V frags ----
#pragma unroll
        for (int ks = 0; ks < 8; ks++) {
            int k0 = ks * 8;
            uint32_t a0[4], a1[4];
            a0[0] = __float_as_uint(Ps[r0 * QP + k0 + q]);
            a0[1] = __float_as_uint(Ps[(r0 + 8) * QP + k0 + q]);
            a0[2] = __float_as_uint(Ps[r0 * QP + k0 + q + 4]);
            a0[3] = __float_as_uint(Ps[(r0 + 8) * QP + k0 + q + 4]);
            a1[0] = __float_as_uint(Ps[r1 * QP + k0 + q]);
            a1[1] = __float_as_uint(Ps[(r1 + 8) * QP + k0 + q]);
            a1[2] = __float_as_uint(Ps[r1 * QP + k0 + q + 4]);
            a1[3] = __float_as_uint(Ps[(r1 + 8) * QP + k0 + q + 4]);
#pragma unroll
            for (int j = 0; j < 8; j++) {
                uint32_t b0 = rtf(Vs[(k0 + q) * VP + j * 8 + g]);
                uint32_t b1 = rtf(Vs[(k0 + q + 4) * VP + j * 8 + g]);
                mma_tf32(oacc0[j], a0, b0, b1);
                mma_tf32(oacc1[j], a1, b0, b1);
            }
        }

        __syncthreads();   // all warps done reading Vs
        if (t0 + 64 < S_) {     // async-stage V(t+1); overlaps next QK^T
#pragma unroll
            for (int t = 0; t < 8; t++) {
                int u = tid + t * 128;
                int rr = u >> 4, cc = (u & 15) * 4;
                cp_async16(sVs + (uint32_t)(rr * VP + cc) * 4u,
                           &V[base + (size_t)(t0 + 64 + rr) * E_ + cc]);
            }
        }
        cp_commit();
    }

    // normalize + write ctx in [B,S,H,D] layout
    float i0a = 1.f / l0a, i0b = 1.f / l0b, i1a = 1.f / l1a, i1b = 1.f / l1b;
#pragma unroll
    for (int j = 0; j < 8; j++) {
        int col = j * 8 + 2 * q;
        *(float2*)&O[base + (size_t)(q0 + r0) * E_ + col] =
            make_float2(oacc0[j][0] * i0a, oacc0[j][1] * i0a);
        *(float2*)&O[base + (size_t)(q0 + r0 + 8) * E_ + col] =
            make_float2(oacc0[j][2] * i0b, oacc0[j][3] * i0b);
        *(float2*)&O[base + (size_t)(q0 + r1) * E_ + col] =
            make_float2(oacc1[j][0] * i1a, oacc1[j][1] * i1a);
        *(float2*)&O[base + (size_t)(q0 + r1 + 8) * E_ + col] =
            make_float2(oacc1[j][2] * i1b, oacc1[j][3] * i1b);
    }
}

// ---------------------------------------------------------------------------
extern "C" void kernel_launch(void* const* d_in, const int* in_sizes, int n_in,
                              void* d_out, int out_size)
{
    const float* X  = (const float*)d_in[0];
    const float* Wq = (const float*)d_in[1];
    const float* Wk = (const float*)d_in[2];
    const float* Wv = (const float*)d_in[3];
    const float* Wo = (const float*)d_in[4];
    const float* bo = (const float*)d_in[5];
    float* out = (float*)d_out;

    float *Qp, *Kp, *Vp, *Cp;
    cudaGetSymbolAddress((void**)&Qp, g_Q);
    cudaGetSymbolAddress((void**)&Kp, g_K);
    cudaGetSymbolAddress((void**)&Vp, g_V);
    cudaGetSymbolAddress((void**)&Cp, g_Ctx);

    int gemm_smem = GEMM_SMEM_FLOATS * (int)sizeof(float);   // 61440
    cudaFuncSetAttribute(gemm_tf32_nt,
                         cudaFuncAttributeMaxDynamicSharedMemorySize, gemm_smem);
    int flash_smem = FLASH_SMEM_FLOATS * (int)sizeof(float); // 105472
    cudaFuncSetAttribute(flash_tf32_kernel,
                         cudaFuncAttributeMaxDynamicSharedMemorySize, flash_smem);

    dim3 gemm_grid(E_ / 128, MTOT / 128);   // (8, 64)
    gemm_tf32_nt<<<gemm_grid, 256, gemm_smem>>>(X, Wq, nullptr, Qp, MTOT, E_, E_);
    gemm_tf32_nt<<<gemm_grid, 256, gemm_smem>>>(X, Wk, nullptr, Kp, MTOT, E_, E_);
    gemm_tf32_nt<<<gemm_grid, 256, gemm_smem>>>(X, Wv, nullptr, Vp, MTOT, E_, E_);

    flash_tf32_kernel<<<dim3(S_ / 128, H_, B_), 128, flash_smem>>>(Qp, Kp, Vp, Cp);

    gemm_tf32_nt<<<gemm_grid, 256, gemm_smem>>>(Cp, Wo, bo, out, MTOT, E_, E_);
}